// round 7
// baseline (speedup 1.0000x reference)
#include <cuda_runtime.h>
#include <math.h>
#include <stdint.h>

// Problem constants
#define NN_   16384      // total nodes (B*N)
#define E_    262144     // edges (no self loops)
#define B_    64         // graphs
#define FIN_  256
#define OUTC_ 256
#define DEP_  64
#define HID_  256
#define G3_   768        // 3*HID

// ---------------- device scratch (no cudaMalloc allowed) ----------------
__device__ float g_Ax  [NN_*OUTC_];     // x @ WA^T                (16 MB)
__device__ float g_deg [NN_];
__device__ float g_dinv[NN_];
__device__ float g_agg [NN_*OUTC_];     // scatter target          (16 MB)
__device__ float g_seqA[NN_*OUTC_];     // GRU ping                (16 MB)
__device__ float g_seqB[NN_*OUTC_];     // GRU pong                (16 MB)
__device__ float g_xp  [NN_*G3_];       // input projections       (48 MB)
__device__ float g_wT  [256*G3_];       // transposed w_hh (float4-grouped rows)
__device__ float g_Bself[OUTC_];
__device__ float g_pool[B_*1280];

// Device-side buffer selection (kernel_launch passes only POD args so the
// host code performs *zero* non-launch CUDA API calls during graph capture).
#define BUF_AX   1
#define BUF_SEQA 2
#define BUF_SEQB 3
#define BUF_XP   4
__device__ __forceinline__ float* pick_buf(int sel) {
    switch (sel) {
        case BUF_AX:   return g_Ax;
        case BUF_SEQA: return g_seqA;
        case BUF_SEQB: return g_seqB;
        default:       return g_xp;
    }
}

// ---------------- math helpers (MUFU-based, ~1e-6 rel err) ----------------
__device__ __forceinline__ float fast_tanh(float x) {
    x = fminf(fmaxf(x, -15.f), 15.f);
    float e = __expf(2.f * x);
    return __fdividef(e - 1.f, e + 1.f);
}
__device__ __forceinline__ float fast_sig(float x) {
    x = fminf(fmaxf(x, -30.f), 30.f);
    return __fdividef(1.f, 1.f + __expf(-x));
}

// ---------------- generic SGEMM: C[M,N] = A[M,K] @ W[N,K]^T (+bias) -------
// BM=128, BN=64, BK=16, 256 threads, 8x4 per-thread tile.
// aSel==0 -> A is the passed pointer; otherwise device scratch buffer.
#define BM 128
#define BN 64
#define BK 16
__global__ void __launch_bounds__(256)
sgemm_nt(const float* __restrict__ Aext, int aSel, const float* __restrict__ W,
         const float* __restrict__ bias, int cSel, int N, int K)
{
    const float* A = (aSel == 0) ? Aext : pick_buf(aSel);
    float* C = pick_buf(cSel);

    __shared__ float As[BK][BM + 4];
    __shared__ float Bs[BK][BN + 4];
    int tid = threadIdx.x;
    int mBase = blockIdx.y * BM;
    int nBase = blockIdx.x * BN;
    int ty = tid >> 4;   // 0..15 -> m offset ty*8
    int tx = tid & 15;   // 0..15 -> n offset tx*4

    float acc[8][4];
#pragma unroll
    for (int i = 0; i < 8; i++)
#pragma unroll
        for (int j = 0; j < 4; j++) acc[i][j] = 0.f;

    for (int kt = 0; kt < K; kt += BK) {
#pragma unroll
        for (int u = 0; u < 2; u++) {
            int v = tid + u * 256;           // 512 float4 of A tile
            int row = v >> 2;
            int kk = (v & 3) * 4;
            float4 a = *reinterpret_cast<const float4*>(&A[(size_t)(mBase + row) * K + kt + kk]);
            As[kk + 0][row] = a.x; As[kk + 1][row] = a.y;
            As[kk + 2][row] = a.z; As[kk + 3][row] = a.w;
        }
        {
            int v = tid;                     // 256 float4 of W tile
            int n = v >> 2;
            int kk = (v & 3) * 4;
            float4 b = *reinterpret_cast<const float4*>(&W[(size_t)(nBase + n) * K + kt + kk]);
            Bs[kk + 0][n] = b.x; Bs[kk + 1][n] = b.y;
            Bs[kk + 2][n] = b.z; Bs[kk + 3][n] = b.w;
        }
        __syncthreads();
#pragma unroll
        for (int k = 0; k < BK; k++) {
            float a[8], b[4];
#pragma unroll
            for (int i = 0; i < 8; i++) a[i] = As[k][ty * 8 + i];
#pragma unroll
            for (int j = 0; j < 4; j++) b[j] = Bs[k][tx * 4 + j];
#pragma unroll
            for (int i = 0; i < 8; i++)
#pragma unroll
                for (int j = 0; j < 4; j++) acc[i][j] = fmaf(a[i], b[j], acc[i][j]);
        }
        __syncthreads();
    }
#pragma unroll
    for (int i = 0; i < 8; i++) {
        int row = mBase + ty * 8 + i;
        int col = nBase + tx * 4;
        float4 r = make_float4(acc[i][0], acc[i][1], acc[i][2], acc[i][3]);
        if (bias) {
            r.x += bias[col + 0]; r.y += bias[col + 1];
            r.z += bias[col + 2]; r.w += bias[col + 3];
        }
        *reinterpret_cast<float4*>(&C[(size_t)row * N + col]) = r;
    }
}

// ---------------- GCN helper kernels ----------------
__global__ void k_init_deg() {
    int i = blockIdx.x * blockDim.x + threadIdx.x;
    if (i < NN_) g_deg[i] = 1.f;                 // self loop
}
__global__ void k_zero_agg() {
    g_agg[(size_t)blockIdx.x * 256 + threadIdx.x] = 0.f;
}
__global__ void k_count(const int* __restrict__ ei) {
    int e = blockIdx.x * blockDim.x + threadIdx.x;
    if (e < E_) atomicAdd(&g_deg[ei[E_ + e]], 1.f);
}
__global__ void k_dinv() {
    int i = blockIdx.x * blockDim.x + threadIdx.x;
    if (i < NN_) g_dinv[i] = rsqrtf(g_deg[i]);
}
__global__ void k_bself(const float* __restrict__ WB) {
    int j = threadIdx.x;
    float s = 0.f;
#pragma unroll
    for (int d = 0; d < DEP_; d++) s += WB[j * DEP_ + d];
    g_Bself[j] = s;
}

// ---------------- fused edge kernel ----------------
// Tile: 64 edges x 64 channels, K=DEP=64 in one shot.
// Be = ea_tile @ WB_tile^T computed in-registers (4x4 per thread),
// epilogue: msg = norm * tanh(Ax[row][c] * Be) -> atomicAdd(agg[col][c]).
__global__ void __launch_bounds__(256)
k_edge_fused(const float* __restrict__ ea, const float* __restrict__ WB,
             const int* __restrict__ ei)
{
    __shared__ float As[64][DEP_ + 1];   // [edge][dep]
    __shared__ float Bs[64][DEP_ + 1];   // [channel][dep]
    int tid = threadIdx.x;
    int mBase = blockIdx.y * 64;         // edge base
    int nBase = blockIdx.x * 64;         // channel base

    // load ea tile: 64x64 floats = 1024 float4, 256 threads -> 4 each
#pragma unroll
    for (int u = 0; u < 4; u++) {
        int v = tid + u * 256;
        int row = v >> 4;                // 16 float4 per row
        int kk = (v & 15) * 4;
        float4 a = *reinterpret_cast<const float4*>(&ea[(size_t)(mBase + row) * DEP_ + kk]);
        As[row][kk + 0] = a.x; As[row][kk + 1] = a.y;
        As[row][kk + 2] = a.z; As[row][kk + 3] = a.w;
    }
    // load WB tile: 64 channels x 64
#pragma unroll
    for (int u = 0; u < 4; u++) {
        int v = tid + u * 256;
        int n = v >> 4;
        int kk = (v & 15) * 4;
        float4 b = *reinterpret_cast<const float4*>(&WB[(size_t)(nBase + n) * DEP_ + kk]);
        Bs[n][kk + 0] = b.x; Bs[n][kk + 1] = b.y;
        Bs[n][kk + 2] = b.z; Bs[n][kk + 3] = b.w;
    }
    __syncthreads();

    int ty = tid >> 4;                   // 0..15 -> edges ty*4..ty*4+3
    int tx = tid & 15;                   // 0..15 -> channels tx*4..tx*4+3
    float acc[4][4];
#pragma unroll
    for (int i = 0; i < 4; i++)
#pragma unroll
        for (int j = 0; j < 4; j++) acc[i][j] = 0.f;

#pragma unroll 8
    for (int k = 0; k < DEP_; k++) {
        float a[4], b[4];
#pragma unroll
        for (int i = 0; i < 4; i++) a[i] = As[ty * 4 + i][k];
#pragma unroll
        for (int j = 0; j < 4; j++) b[j] = Bs[tx * 4 + j][k];
#pragma unroll
        for (int i = 0; i < 4; i++)
#pragma unroll
            for (int j = 0; j < 4; j++) acc[i][j] = fmaf(a[i], b[j], acc[i][j]);
    }

    // epilogue: gather Ax, tanh, scatter-add
#pragma unroll
    for (int i = 0; i < 4; i++) {
        int e = mBase + ty * 4 + i;
        int row = ei[e];
        int col = ei[E_ + e];
        float norm = g_dinv[row] * g_dinv[col];
        const float* axp = &g_Ax[(size_t)row * 256 + nBase + tx * 4];
        float* aggp = &g_agg[(size_t)col * 256 + nBase + tx * 4];
#pragma unroll
        for (int j = 0; j < 4; j++)
            atomicAdd(&aggp[j], norm * fast_tanh(axp[j] * acc[i][j]));
    }
}

__global__ void k_final_node(const float* __restrict__ bias) {
    int i = blockIdx.x;
    int j = threadIdx.x;
    float dv = g_dinv[i];
    size_t idx = (size_t)i * 256 + j;
    float self = dv * dv * fast_tanh(g_Ax[idx] * g_Bself[j]);
    float v = (g_agg[idx] + self) * __fdividef(1.f, g_deg[i]);
    g_seqA[idx] = fast_tanh(v + bias[j]);
}

// ---------------- GRU ----------------
// transpose w_hh [768,256] -> g_wT so that
// ((float4*)g_wT)[k*192 + q] = { w[4q][k], w[4q+1][k], w[4q+2][k], w[4q+3][k] }
__global__ void k_wt(const float* __restrict__ w) {
    int idx = blockIdx.x * blockDim.x + threadIdx.x;   // 196608
    int c = idx & 3;
    int q = (idx >> 2) % 192;
    int k = idx / 768;
    g_wT[idx] = w[(4 * q + c) * 256 + k];
}

// one block = 2 graphs; 192 threads; 256 timesteps with __syncthreads phases
__global__ void __launch_bounds__(192, 1)
k_gru(const float* __restrict__ b_hh, int outSel, int layer)
{
    const float* xp = g_xp;
    float* seq_out = pick_buf(outSel);

    __shared__ float2 h_s[256];          // [k] -> (h_graph0, h_graph1)
    __shared__ float4 gh4[2][192];       // gh rows grouped by 4
    int tid = threadIdx.x;               // 0..191
    int b0 = blockIdx.x * 2;
    const float4* wT4 = reinterpret_cast<const float4*>(g_wT);
    float4 bh = reinterpret_cast<const float4*>(b_hh)[tid];

    for (int k = tid; k < 256; k += 192) h_s[k] = make_float2(0.f, 0.f);
    __syncthreads();

    for (int t = 0; t < 256; t++) {
        // phase 1: gh[j] = b_hh[j] + sum_k w_hh[j][k]*h[k]  (rows 4*tid..4*tid+3)
        float4 a0 = bh, a1 = bh;
#pragma unroll 8
        for (int k = 0; k < 256; k++) {
            float4 w = wT4[k * 192 + tid];
            float2 h = h_s[k];
            a0.x = fmaf(w.x, h.x, a0.x); a0.y = fmaf(w.y, h.x, a0.y);
            a0.z = fmaf(w.z, h.x, a0.z); a0.w = fmaf(w.w, h.x, a0.w);
            a1.x = fmaf(w.x, h.y, a1.x); a1.y = fmaf(w.y, h.y, a1.y);
            a1.z = fmaf(w.z, h.y, a1.z); a1.w = fmaf(w.w, h.y, a1.w);
        }
        gh4[0][tid] = a0;
        gh4[1][tid] = a1;
        __syncthreads();

        // phase 2: gate combine + h update
        const float* gh0 = reinterpret_cast<const float*>(gh4[0]);
        const float* gh1 = reinterpret_cast<const float*>(gh4[1]);
        for (int j = tid; j < 256; j += 192) {
            {   // graph 0
                const float* x = &xp[((size_t)(b0 + 0) * 256 + t) * 768];
                float r = fast_sig(x[j] + gh0[j]);
                float z = fast_sig(x[256 + j] + gh0[256 + j]);
                float n = fast_tanh(x[512 + j] + r * gh0[512 + j]);
                float hn = (1.f - z) * n + z * h_s[j].x;
                h_s[j].x = hn;
                seq_out[((size_t)(b0 + 0) * 256 + t) * 256 + j] = hn;
            }
            {   // graph 1
                const float* x = &xp[((size_t)(b0 + 1) * 256 + t) * 768];
                float r = fast_sig(x[j] + gh1[j]);
                float z = fast_sig(x[256 + j] + gh1[256 + j]);
                float n = fast_tanh(x[512 + j] + r * gh1[512 + j]);
                float hn = (1.f - z) * n + z * h_s[j].y;
                h_s[j].y = hn;
                seq_out[((size_t)(b0 + 1) * 256 + t) * 256 + j] = hn;
            }
        }
        __syncthreads();
    }

    for (int j = tid; j < 256; j += 192) {
        g_pool[(b0 + 0) * 1280 + layer * 256 + j] = h_s[j].x;
        g_pool[(b0 + 1) * 1280 + layer * 256 + j] = h_s[j].y;
    }
}

// ---------------- pooling + head ----------------
__global__ void k_pool(int seqSel) {
    const float* seq = pick_buf(seqSel);
    int b = blockIdx.x, j = threadIdx.x;
    float m = -1e30f, s = 0.f;
    for (int t = 0; t < 256; t++) {
        float v = seq[((size_t)b * 256 + t) * 256 + j];
        m = fmaxf(m, v);
        s += v;
    }
    g_pool[b * 1280 + 768 + j] = m;
    g_pool[b * 1280 + 1024 + j] = s * (1.f / 256.f);
}

__global__ void k_head(const float* __restrict__ linW, const float* __restrict__ linb,
                       float* __restrict__ out)
{
    __shared__ float red0[128], red1[128];
    int b = blockIdx.x, tid = threadIdx.x;   // 128 threads
    float p0 = 0.f, p1 = 0.f;
    for (int i = tid; i < 1280; i += 128) {
        float pv = g_pool[b * 1280 + i];
        p0 = fmaf(pv, linW[i], p0);
        p1 = fmaf(pv, linW[1280 + i], p1);
    }
    red0[tid] = p0; red1[tid] = p1;
    __syncthreads();
    for (int s = 64; s > 0; s >>= 1) {
        if (tid < s) { red0[tid] += red0[tid + s]; red1[tid] += red1[tid + s]; }
        __syncthreads();
    }
    if (tid == 0) {
        float l0 = red0[0] + linb[0];
        float l1 = red1[0] + linb[1];
        float mm = fmaxf(l0, l1);
        float e0 = __expf(l0 - mm), e1 = __expf(l1 - mm);
        float inv = __fdividef(1.f, e0 + e1);
        out[b * 2 + 0] = e0 * inv;
        out[b * 2 + 1] = e1 * inv;
    }
}

// ---------------- launch (ONLY kernel launches — capture-clean) ----------------
extern "C" void kernel_launch(void* const* d_in, const int* in_sizes, int n_in,
                              void* d_out, int out_size)
{
    (void)in_sizes; (void)n_in; (void)out_size;
    const float* x    = (const float*)d_in[0];
    const float* ea   = (const float*)d_in[1];
    const int*   ei   = (const int*)  d_in[2];
    const float* WA   = (const float*)d_in[3];
    const float* WB   = (const float*)d_in[4];
    const float* gb   = (const float*)d_in[5];
    const float* wih[3] = {(const float*)d_in[6],  (const float*)d_in[10], (const float*)d_in[14]};
    const float* whh[3] = {(const float*)d_in[7],  (const float*)d_in[11], (const float*)d_in[15]};
    const float* bih[3] = {(const float*)d_in[8],  (const float*)d_in[12], (const float*)d_in[16]};
    const float* bhh[3] = {(const float*)d_in[9],  (const float*)d_in[13], (const float*)d_in[17]};
    const float* linW = (const float*)d_in[18];
    const float* linb = (const float*)d_in[19];
    float* out = (float*)d_out;

    // ---- GCN ----
    k_init_deg<<<NN_ / 256, 256>>>();
    k_zero_agg<<<NN_, 256>>>();
    k_count<<<E_ / 256, 256>>>(ei);
    k_dinv<<<NN_ / 256, 256>>>();
    sgemm_nt<<<dim3(OUTC_ / BN, NN_ / BM), 256>>>(x, 0, WA, nullptr, BUF_AX, OUTC_, FIN_);
    k_bself<<<1, 256>>>(WB);
    k_edge_fused<<<dim3(OUTC_ / 64, E_ / 64), 256>>>(ea, WB, ei);
    k_final_node<<<NN_, 256>>>(gb);

    // ---- GRU: 3 layers (ping-pong seqA <-> seqB) ----
    int sin = BUF_SEQA, sout = BUF_SEQB;
    for (int l = 0; l < 3; l++) {
        k_wt<<<G3_, 256>>>(whh[l]);
        sgemm_nt<<<dim3(G3_ / BN, NN_ / BM), 256>>>(nullptr, sin, wih[l], bih[l], BUF_XP, G3_, 256);
        k_gru<<<B_ / 2, 192>>>(bhh[l], sout, l);
        int tmp = sin; sin = sout; sout = tmp;
    }
    // after 3 swaps, final layer output is in `sin`

    // ---- pool + head ----
    k_pool<<<B_, 256>>>(sin);
    k_head<<<B_, 128>>>(linW, linb, out);
}

// round 10
// speedup vs baseline: 1.4116x; 1.4116x over previous
#include <cuda_runtime.h>
#include <math.h>
#include <stdint.h>

// Problem constants
#define NN_   16384      // total nodes (B*N)
#define E_    262144     // edges (no self loops)
#define B_    64         // graphs
#define FIN_  256
#define OUTC_ 256
#define DEP_  64
#define HID_  256
#define G3_   768        // 3*HID

// ---------------- device scratch (no cudaMalloc allowed) ----------------
__device__ float g_Ax  [NN_*OUTC_];     // x @ WA^T                (16 MB)
__device__ float g_deg [NN_];
__device__ float g_dinv[NN_];
__device__ float g_agg [NN_*OUTC_];     // scatter target          (16 MB)
__device__ float g_seqA[NN_*OUTC_];     // GRU ping                (16 MB)
__device__ float g_seqB[NN_*OUTC_];     // GRU pong                (16 MB)
__device__ float g_xp  [NN_*G3_];       // input projections       (48 MB)
__device__ float g_wT  [256*G3_];       // k-vectorized w_hh: float4[k4*768 + r]
__device__ float g_Bself[OUTC_];
__device__ float g_pool[B_*1280];

// Device-side buffer selection: host passes only POD selectors so kernel_launch
// performs zero non-launch CUDA API calls (capture-clean).
#define BUF_AX   1
#define BUF_SEQA 2
#define BUF_SEQB 3
#define BUF_XP   4
__device__ __forceinline__ float* pick_buf(int sel) {
    switch (sel) {
        case BUF_AX:   return g_Ax;
        case BUF_SEQA: return g_seqA;
        case BUF_SEQB: return g_seqB;
        default:       return g_xp;
    }
}

// ---------------- math helpers (MUFU-based, ~1e-6 rel err) ----------------
__device__ __forceinline__ float fast_tanh(float x) {
    x = fminf(fmaxf(x, -15.f), 15.f);
    float e = __expf(2.f * x);
    return __fdividef(e - 1.f, e + 1.f);
}
__device__ __forceinline__ float fast_sig(float x) {
    x = fminf(fmaxf(x, -30.f), 30.f);
    return __fdividef(1.f, 1.f + __expf(-x));
}

// ---------------- SGEMM 128x128, 8x8/thread: C[M,N] = A[M,K] @ W[N,K]^T ----
// 256 threads; BK=16. Requires M%128==0, N%128==0, K%16==0.
#define BM2 128
#define BN2 128
#define BK2 16
__global__ void __launch_bounds__(256)
sgemm2(const float* __restrict__ Aext, int aSel, const float* __restrict__ W,
       const float* __restrict__ bias, int cSel, int N, int K)
{
    const float* A = (aSel == 0) ? Aext : pick_buf(aSel);
    float* C = pick_buf(cSel);

    __shared__ float As[BK2][BM2 + 4];
    __shared__ float Bs[BK2][BN2 + 4];
    int tid = threadIdx.x;
    int mBase = blockIdx.y * BM2;
    int nBase = blockIdx.x * BN2;
    int ty = tid >> 4;   // 0..15 -> rows ty*8..ty*8+7
    int tx = tid & 15;   // 0..15 -> cols tx*8..tx*8+7

    float acc[8][8];
#pragma unroll
    for (int i = 0; i < 8; i++)
#pragma unroll
        for (int j = 0; j < 8; j++) acc[i][j] = 0.f;

    for (int kt = 0; kt < K; kt += BK2) {
#pragma unroll
        for (int u = 0; u < 2; u++) {
            int v = tid + u * 256;           // 512 float4 for A tile
            int row = v >> 2;
            int kk = (v & 3) * 4;
            float4 a = *reinterpret_cast<const float4*>(&A[(size_t)(mBase + row) * K + kt + kk]);
            As[kk + 0][row] = a.x; As[kk + 1][row] = a.y;
            As[kk + 2][row] = a.z; As[kk + 3][row] = a.w;
        }
#pragma unroll
        for (int u = 0; u < 2; u++) {
            int v = tid + u * 256;           // 512 float4 for W tile
            int n = v >> 2;
            int kk = (v & 3) * 4;
            float4 b = *reinterpret_cast<const float4*>(&W[(size_t)(nBase + n) * K + kt + kk]);
            Bs[kk + 0][n] = b.x; Bs[kk + 1][n] = b.y;
            Bs[kk + 2][n] = b.z; Bs[kk + 3][n] = b.w;
        }
        __syncthreads();
#pragma unroll
        for (int k = 0; k < BK2; k++) {
            float a[8], b[8];
            float4 a0 = *reinterpret_cast<const float4*>(&As[k][ty * 8]);
            float4 a1 = *reinterpret_cast<const float4*>(&As[k][ty * 8 + 4]);
            float4 b0 = *reinterpret_cast<const float4*>(&Bs[k][tx * 8]);
            float4 b1 = *reinterpret_cast<const float4*>(&Bs[k][tx * 8 + 4]);
            a[0]=a0.x; a[1]=a0.y; a[2]=a0.z; a[3]=a0.w;
            a[4]=a1.x; a[5]=a1.y; a[6]=a1.z; a[7]=a1.w;
            b[0]=b0.x; b[1]=b0.y; b[2]=b0.z; b[3]=b0.w;
            b[4]=b1.x; b[5]=b1.y; b[6]=b1.z; b[7]=b1.w;
#pragma unroll
            for (int i = 0; i < 8; i++)
#pragma unroll
                for (int j = 0; j < 8; j++) acc[i][j] = fmaf(a[i], b[j], acc[i][j]);
        }
        __syncthreads();
    }
#pragma unroll
    for (int i = 0; i < 8; i++) {
        int row = mBase + ty * 8 + i;
        int col = nBase + tx * 8;
#pragma unroll
        for (int h = 0; h < 2; h++) {
            float4 r = make_float4(acc[i][h*4+0], acc[i][h*4+1], acc[i][h*4+2], acc[i][h*4+3]);
            if (bias) {
                r.x += bias[col + h*4 + 0]; r.y += bias[col + h*4 + 1];
                r.z += bias[col + h*4 + 2]; r.w += bias[col + h*4 + 3];
            }
            *reinterpret_cast<float4*>(&C[(size_t)row * N + col + h*4]) = r;
        }
    }
}

// ---------------- GCN helper kernels ----------------
// prep: zero agg, deg=1 (self loop)
__global__ void k_prep() {
    int b = blockIdx.x, j = threadIdx.x;
    g_agg[(size_t)b * 256 + j] = 0.f;
    if (j == 0) g_deg[b] = 1.f;
}
__global__ void k_count(const int* __restrict__ ei) {
    int e = blockIdx.x * blockDim.x + threadIdx.x;
    if (e < E_) atomicAdd(&g_deg[ei[E_ + e]], 1.f);
}
// blocks 0..63: dinv; block 64: Bself
__global__ void k_dinv2(const float* __restrict__ WB) {
    if (blockIdx.x < 64) {
        int i = blockIdx.x * 256 + threadIdx.x;
        g_dinv[i] = rsqrtf(g_deg[i]);
    } else {
        int j = threadIdx.x;
        float s = 0.f;
#pragma unroll
        for (int d = 0; d < DEP_; d++) s += WB[j * DEP_ + d];
        g_Bself[j] = s;
    }
}

// ---------------- fused edge kernel ----------------
// Tile: 64 edges x 64 channels, K=DEP=64.
// Be = ea_tile @ WB_tile^T in-registers (4x4/thread),
// epilogue: msg = norm*tanh(Ax[row][c]*Be) -> atomicAdd(agg[col][c]).
__global__ void __launch_bounds__(256)
k_edge_fused(const float* __restrict__ ea, const float* __restrict__ WB,
             const int* __restrict__ ei)
{
    __shared__ float As[64][DEP_ + 1];   // [edge][dep]
    __shared__ float Bs[64][DEP_ + 1];   // [channel][dep]
    int tid = threadIdx.x;
    int mBase = blockIdx.y * 64;         // edge base
    int nBase = blockIdx.x * 64;         // channel base

#pragma unroll
    for (int u = 0; u < 4; u++) {
        int v = tid + u * 256;
        int row = v >> 4;
        int kk = (v & 15) * 4;
        float4 a = *reinterpret_cast<const float4*>(&ea[(size_t)(mBase + row) * DEP_ + kk]);
        As[row][kk + 0] = a.x; As[row][kk + 1] = a.y;
        As[row][kk + 2] = a.z; As[row][kk + 3] = a.w;
    }
#pragma unroll
    for (int u = 0; u < 4; u++) {
        int v = tid + u * 256;
        int n = v >> 4;
        int kk = (v & 15) * 4;
        float4 b = *reinterpret_cast<const float4*>(&WB[(size_t)(nBase + n) * DEP_ + kk]);
        Bs[n][kk + 0] = b.x; Bs[n][kk + 1] = b.y;
        Bs[n][kk + 2] = b.z; Bs[n][kk + 3] = b.w;
    }
    __syncthreads();

    int ty = tid >> 4;                   // edges ty*4..+3
    int tx = tid & 15;                   // channels tx*4..+3
    float acc[4][4];
#pragma unroll
    for (int i = 0; i < 4; i++)
#pragma unroll
        for (int j = 0; j < 4; j++) acc[i][j] = 0.f;

#pragma unroll 8
    for (int k = 0; k < DEP_; k++) {
        float a[4], b[4];
#pragma unroll
        for (int i = 0; i < 4; i++) a[i] = As[ty * 4 + i][k];
#pragma unroll
        for (int j = 0; j < 4; j++) b[j] = Bs[tx * 4 + j][k];
#pragma unroll
        for (int i = 0; i < 4; i++)
#pragma unroll
            for (int j = 0; j < 4; j++) acc[i][j] = fmaf(a[i], b[j], acc[i][j]);
    }

#pragma unroll
    for (int i = 0; i < 4; i++) {
        int e = mBase + ty * 4 + i;
        int row = ei[e];
        int col = ei[E_ + e];
        float norm = g_dinv[row] * g_dinv[col];
        const float* axp = &g_Ax[(size_t)row * 256 + nBase + tx * 4];
        float* aggp = &g_agg[(size_t)col * 256 + nBase + tx * 4];
#pragma unroll
        for (int j = 0; j < 4; j++)
            atomicAdd(&aggp[j], norm * fast_tanh(axp[j] * acc[i][j]));
    }
}

__global__ void k_final_node(const float* __restrict__ bias) {
    int i = blockIdx.x;
    int j = threadIdx.x;
    float dv = g_dinv[i];
    size_t idx = (size_t)i * 256 + j;
    float self = dv * dv * fast_tanh(g_Ax[idx] * g_Bself[j]);
    float v = (g_agg[idx] + self) * __fdividef(1.f, g_deg[i]);
    g_seqA[idx] = fast_tanh(v + bias[j]);
}

// ---------------- GRU ----------------
// weight transform: g_wT viewed as float4[k4*768 + r] = {w[r][4k4..4k4+3]}
// linear float idx = (k4*768 + r)*4 + c  <-  w[r*256 + 4*k4 + c]
__global__ void k_wt(const float* __restrict__ w) {
    int idx = blockIdx.x * blockDim.x + threadIdx.x;   // 196608
    int c = idx & 3;
    int tmp = idx >> 2;
    int r = tmp % 768;
    int k4 = tmp / 768;
    g_wT[idx] = w[r * 256 + 4 * k4 + c];
}

// one block = 2 graphs; 256 threads (balanced 2 warps/SMSP); thread j owns
// gate rows {j, 256+j, 512+j}; all gate accumulators in registers.
__global__ void __launch_bounds__(256, 1)
k_gru(const float* __restrict__ b_hh, int outSel, int layer)
{
    float* seq_out = pick_buf(outSel);
    __shared__ float h0[256], h1[256];
    int j = threadIdx.x;
    int b0 = blockIdx.x * 2;
    const float4* wt = reinterpret_cast<const float4*>(g_wT);
    const float4* h0v = reinterpret_cast<const float4*>(h0);
    const float4* h1v = reinterpret_cast<const float4*>(h1);

    float bR = b_hh[j], bZ = b_hh[256 + j], bN = b_hh[512 + j];
    const float* xp0 = g_xp + (size_t)(b0 + 0) * 256 * 768;
    const float* xp1 = g_xp + (size_t)(b0 + 1) * 256 * 768;

    h0[j] = 0.f; h1[j] = 0.f;
    __syncthreads();

    float hn0 = 0.f, hn1 = 0.f;
    for (int t = 0; t < 256; t++) {
        float aR0 = bR, aZ0 = bZ, aN0 = bN;
        float aR1 = bR, aZ1 = bZ, aN1 = bN;
#pragma unroll 4
        for (int k4 = 0; k4 < 64; k4++) {
            float4 w0 = wt[k4 * 768 + j];          // r-gate row j
            float4 w1 = wt[k4 * 768 + 256 + j];    // z-gate
            float4 w2 = wt[k4 * 768 + 512 + j];    // n-gate
            float4 ha = h0v[k4];
            float4 hb = h1v[k4];
            aR0 = fmaf(w0.x, ha.x, aR0); aR0 = fmaf(w0.y, ha.y, aR0);
            aR0 = fmaf(w0.z, ha.z, aR0); aR0 = fmaf(w0.w, ha.w, aR0);
            aZ0 = fmaf(w1.x, ha.x, aZ0); aZ0 = fmaf(w1.y, ha.y, aZ0);
            aZ0 = fmaf(w1.z, ha.z, aZ0); aZ0 = fmaf(w1.w, ha.w, aZ0);
            aN0 = fmaf(w2.x, ha.x, aN0); aN0 = fmaf(w2.y, ha.y, aN0);
            aN0 = fmaf(w2.z, ha.z, aN0); aN0 = fmaf(w2.w, ha.w, aN0);
            aR1 = fmaf(w0.x, hb.x, aR1); aR1 = fmaf(w0.y, hb.y, aR1);
            aR1 = fmaf(w0.z, hb.z, aR1); aR1 = fmaf(w0.w, hb.w, aR1);
            aZ1 = fmaf(w1.x, hb.x, aZ1); aZ1 = fmaf(w1.y, hb.y, aZ1);
            aZ1 = fmaf(w1.z, hb.z, aZ1); aZ1 = fmaf(w1.w, hb.w, aZ1);
            aN1 = fmaf(w2.x, hb.x, aN1); aN1 = fmaf(w2.y, hb.y, aN1);
            aN1 = fmaf(w2.z, hb.z, aN1); aN1 = fmaf(w2.w, hb.w, aN1);
        }
        const float* x0 = xp0 + (size_t)t * 768;
        const float* x1 = xp1 + (size_t)t * 768;
        {
            float r = fast_sig(x0[j] + aR0);
            float z = fast_sig(x0[256 + j] + aZ0);
            float n = fast_tanh(x0[512 + j] + r * aN0);
            hn0 = (1.f - z) * n + z * h0[j];
        }
        {
            float r = fast_sig(x1[j] + aR1);
            float z = fast_sig(x1[256 + j] + aZ1);
            float n = fast_tanh(x1[512 + j] + r * aN1);
            hn1 = (1.f - z) * n + z * h1[j];
        }
        __syncthreads();               // all reads of h done
        h0[j] = hn0; h1[j] = hn1;
        seq_out[((size_t)(b0 + 0) * 256 + t) * 256 + j] = hn0;
        seq_out[((size_t)(b0 + 1) * 256 + t) * 256 + j] = hn1;
        __syncthreads();               // writes visible before next step reads
    }

    g_pool[(b0 + 0) * 1280 + layer * 256 + j] = hn0;
    g_pool[(b0 + 1) * 1280 + layer * 256 + j] = hn1;
}

// ---------------- pooling + head ----------------
__global__ void k_pool(int seqSel) {
    const float* seq = pick_buf(seqSel);
    int b = blockIdx.x, j = threadIdx.x;
    float m = -1e30f, s = 0.f;
#pragma unroll 4
    for (int t = 0; t < 256; t++) {
        float v = seq[((size_t)b * 256 + t) * 256 + j];
        m = fmaxf(m, v);
        s += v;
    }
    g_pool[b * 1280 + 768 + j] = m;
    g_pool[b * 1280 + 1024 + j] = s * (1.f / 256.f);
}

__global__ void k_head(const float* __restrict__ linW, const float* __restrict__ linb,
                       float* __restrict__ out)
{
    __shared__ float red0[128], red1[128];
    int b = blockIdx.x, tid = threadIdx.x;   // 128 threads
    float p0 = 0.f, p1 = 0.f;
    for (int i = tid; i < 1280; i += 128) {
        float pv = g_pool[b * 1280 + i];
        p0 = fmaf(pv, linW[i], p0);
        p1 = fmaf(pv, linW[1280 + i], p1);
    }
    red0[tid] = p0; red1[tid] = p1;
    __syncthreads();
    for (int s = 64; s > 0; s >>= 1) {
        if (tid < s) { red0[tid] += red0[tid + s]; red1[tid] += red1[tid + s]; }
        __syncthreads();
    }
    if (tid == 0) {
        float l0 = red0[0] + linb[0];
        float l1 = red1[0] + linb[1];
        float mm = fmaxf(l0, l1);
        float e0 = __expf(l0 - mm), e1 = __expf(l1 - mm);
        float inv = __fdividef(1.f, e0 + e1);
        out[b * 2 + 0] = e0 * inv;
        out[b * 2 + 1] = e1 * inv;
    }
}

// ---------------- launch (ONLY kernel launches — capture-clean) ----------------
extern "C" void kernel_launch(void* const* d_in, const int* in_sizes, int n_in,
                              void* d_out, int out_size)
{
    (void)in_sizes; (void)n_in; (void)out_size;
    const float* x    = (const float*)d_in[0];
    const float* ea   = (const float*)d_in[1];
    const int*   ei   = (const int*)  d_in[2];
    const float* WA   = (const float*)d_in[3];
    const float* WB   = (const float*)d_in[4];
    const float* gb   = (const float*)d_in[5];
    const float* wih[3] = {(const float*)d_in[6],  (const float*)d_in[10], (const float*)d_in[14]};
    const float* whh[3] = {(const float*)d_in[7],  (const float*)d_in[11], (const float*)d_in[15]};
    const float* bih[3] = {(const float*)d_in[8],  (const float*)d_in[12], (const float*)d_in[16]};
    const float* bhh[3] = {(const float*)d_in[9],  (const float*)d_in[13], (const float*)d_in[17]};
    const float* linW = (const float*)d_in[18];
    const float* linb = (const float*)d_in[19];
    float* out = (float*)d_out;

    // ---- GCN (heavy kernels at launch positions 4,5 for ncu sampling) ----
    k_prep <<<NN_, 256>>>();                                                       // 1
    k_count<<<E_ / 256, 256>>>(ei);                                                // 2
    k_dinv2<<<65, 256>>>(WB);                                                      // 3
    sgemm2 <<<dim3(OUTC_ / BN2, NN_ / BM2), 256>>>(x, 0, WA, nullptr, BUF_AX,
                                                   OUTC_, FIN_);                   // 4
    k_edge_fused<<<dim3(OUTC_ / 64, E_ / 64), 256>>>(ea, WB, ei);                  // 5
    k_wt<<<G3_, 256>>>(whh[0]);                                                    // 6
    k_final_node<<<NN_, 256>>>(gb);                                                // 7

    // ---- GRU: 3 layers (ping-pong seqA <-> seqB) ----
    int sin = BUF_SEQA, sout = BUF_SEQB;
    for (int l = 0; l < 3; l++) {
        if (l > 0) k_wt<<<G3_, 256>>>(whh[l]);   // layer-0 transform done above
        sgemm2<<<dim3(G3_ / BN2, NN_ / BM2), 256>>>(nullptr, sin, wih[l], bih[l],
                                                    BUF_XP, G3_, 256);
        k_gru<<<B_ / 2, 256>>>(bhh[l], sout, l);
        int tmp = sin; sin = sout; sout = tmp;
    }
    // final layer output in `sin`

    // ---- pool + head ----
    k_pool<<<B_, 256>>>(sin);
    k_head<<<B_, 128>>>(linW, linb, out);
}

// round 11
// speedup vs baseline: 1.6145x; 1.1437x over previous
#include <cuda_runtime.h>
#include <math.h>
#include <stdint.h>

// Problem constants
#define NN_   16384      // total nodes (B*N)
#define E_    262144     // edges (no self loops)
#define B_    64         // graphs
#define FIN_  256
#define OUTC_ 256
#define DEP_  64
#define HID_  256
#define G3_   768        // 3*HID

// ---------------- device scratch (no cudaMalloc allowed) ----------------
__device__ __align__(16) float g_Ax  [NN_*OUTC_];
__device__ float g_deg [NN_];
__device__ float g_dinv[NN_];
__device__ __align__(16) float g_agg [NN_*OUTC_];
__device__ __align__(16) float g_seqA[NN_*OUTC_];
__device__ __align__(16) float g_seqB[NN_*OUTC_];
__device__ __align__(16) float g_xp  [NN_*G3_];
__device__ __align__(16) float g_wT  [256*G3_];   // k-vectorized w_hh
__device__ float g_Bself[OUTC_];
__device__ float g_pool[B_*1280];

// Device-side buffer selection (capture-clean host path: POD args only).
#define BUF_AX   1
#define BUF_SEQA 2
#define BUF_SEQB 3
#define BUF_XP   4
__device__ __forceinline__ float* pick_buf(int sel) {
    switch (sel) {
        case BUF_AX:   return g_Ax;
        case BUF_SEQA: return g_seqA;
        case BUF_SEQB: return g_seqB;
        default:       return g_xp;
    }
}

// ---------------- packed f32x2 helpers ----------------
__device__ __forceinline__ void ffma2(unsigned long long &d,
                                      unsigned long long a,
                                      unsigned long long b) {
    asm("fma.rn.f32x2 %0, %1, %2, %0;" : "+l"(d) : "l"(a), "l"(b));
}
__device__ __forceinline__ float hadd2(unsigned long long v) {
    float lo, hi;
    asm("mov.b64 {%0, %1}, %2;" : "=f"(lo), "=f"(hi) : "l"(v));
    return lo + hi;
}

// ---------------- math helpers (MUFU-based, ~1e-6 rel err) ----------------
__device__ __forceinline__ float fast_tanh(float x) {
    x = fminf(fmaxf(x, -15.f), 15.f);
    float e = __expf(2.f * x);
    return __fdividef(e - 1.f, e + 1.f);
}
__device__ __forceinline__ float fast_sig(float x) {
    x = fminf(fmaxf(x, -30.f), 30.f);
    return __fdividef(1.f, 1.f + __expf(-x));
}

// ---------------- SGEMM (FFMA2 k-packed): C[M,N] = A[M,K] @ W[N,K]^T ------
// BM=128, BN=64, BK=16; 256 threads; per-thread 8 rows x 4 strided cols.
// acc2[i][jl] packs (even-k sum, odd-k sum); horizontal add in epilogue.
#define BM2 128
#define BN2 64
#define BK2 16
__global__ void __launch_bounds__(256)
sgemm2(const float* __restrict__ Aext, int aSel, const float* __restrict__ W,
       const float* __restrict__ bias, int cSel, int N, int K)
{
    const float* A = (aSel == 0) ? Aext : pick_buf(aSel);
    float* C = pick_buf(cSel);

    __shared__ __align__(16) float As[BM2][20];   // row-major, k contiguous
    __shared__ __align__(16) float Bs[BN2][18];   // row-major, k contiguous
    int tid = threadIdx.x;
    int mBase = blockIdx.y * BM2;
    int nBase = blockIdx.x * BN2;
    int ty = tid >> 4;   // 0..15 -> rows ty*8..ty*8+7
    int tx = tid & 15;   // cols tx + 16*jl (strided: conflict-free b reads)

    unsigned long long acc[8][4];
#pragma unroll
    for (int i = 0; i < 8; i++)
#pragma unroll
        for (int jl = 0; jl < 4; jl++) acc[i][jl] = 0ull;

    for (int kt = 0; kt < K; kt += BK2) {
#pragma unroll
        for (int u = 0; u < 2; u++) {
            int v = tid + u * 256;           // 512 float4 for A tile
            int row = v >> 2;
            int kk = (v & 3) * 4;
            float4 a = *reinterpret_cast<const float4*>(&A[(size_t)(mBase + row) * K + kt + kk]);
            *reinterpret_cast<float4*>(&As[row][kk]) = a;   // (row*20+kk)%4==0 -> 16B aligned
        }
        {
            int v = tid;                     // 256 float4 for W tile
            int n = v >> 2;
            int kk = (v & 3) * 4;
            float4 b = *reinterpret_cast<const float4*>(&W[(size_t)(nBase + n) * K + kt + kk]);
            *reinterpret_cast<float2*>(&Bs[n][kk])     = make_float2(b.x, b.y);
            *reinterpret_cast<float2*>(&Bs[n][kk + 2]) = make_float2(b.z, b.w);
        }
        __syncthreads();
#pragma unroll
        for (int k2 = 0; k2 < BK2 / 2; k2++) {
            unsigned long long a2[8], b2[4];
#pragma unroll
            for (int i = 0; i < 8; i++)
                a2[i] = *reinterpret_cast<const unsigned long long*>(&As[ty * 8 + i][2 * k2]);
#pragma unroll
            for (int jl = 0; jl < 4; jl++)
                b2[jl] = *reinterpret_cast<const unsigned long long*>(&Bs[tx + 16 * jl][2 * k2]);
#pragma unroll
            for (int i = 0; i < 8; i++)
#pragma unroll
                for (int jl = 0; jl < 4; jl++) ffma2(acc[i][jl], a2[i], b2[jl]);
        }
        __syncthreads();
    }
#pragma unroll
    for (int i = 0; i < 8; i++) {
        int row = mBase + ty * 8 + i;
#pragma unroll
        for (int jl = 0; jl < 4; jl++) {
            int col = nBase + tx + 16 * jl;
            float r = hadd2(acc[i][jl]);
            if (bias) r += bias[col];
            C[(size_t)row * N + col] = r;
        }
    }
}

// ---------------- GCN helper kernels ----------------
__global__ void k_prep() {
    int b = blockIdx.x, j = threadIdx.x;
    g_agg[(size_t)b * 256 + j] = 0.f;
    if (j == 0) g_deg[b] = 1.f;                 // self loop
}
__global__ void k_count(const int* __restrict__ ei) {
    int e = blockIdx.x * blockDim.x + threadIdx.x;
    if (e < E_) atomicAdd(&g_deg[ei[E_ + e]], 1.f);
}
__global__ void k_dinv2(const float* __restrict__ WB) {
    if (blockIdx.x < 64) {
        int i = blockIdx.x * 256 + threadIdx.x;
        g_dinv[i] = rsqrtf(g_deg[i]);
    } else {
        int j = threadIdx.x;
        float s = 0.f;
#pragma unroll
        for (int d = 0; d < DEP_; d++) s += WB[j * DEP_ + d];
        g_Bself[j] = s;
    }
}

// ---------------- fused edge kernel (unchanged this round) ----------------
__global__ void __launch_bounds__(256)
k_edge_fused(const float* __restrict__ ea, const float* __restrict__ WB,
             const int* __restrict__ ei)
{
    __shared__ float As[64][DEP_ + 1];   // [edge][dep]
    __shared__ float Bs[64][DEP_ + 1];   // [channel][dep]
    int tid = threadIdx.x;
    int mBase = blockIdx.y * 64;         // edge base
    int nBase = blockIdx.x * 64;         // channel base

#pragma unroll
    for (int u = 0; u < 4; u++) {
        int v = tid + u * 256;
        int row = v >> 4;
        int kk = (v & 15) * 4;
        float4 a = *reinterpret_cast<const float4*>(&ea[(size_t)(mBase + row) * DEP_ + kk]);
        As[row][kk + 0] = a.x; As[row][kk + 1] = a.y;
        As[row][kk + 2] = a.z; As[row][kk + 3] = a.w;
    }
#pragma unroll
    for (int u = 0; u < 4; u++) {
        int v = tid + u * 256;
        int n = v >> 4;
        int kk = (v & 15) * 4;
        float4 b = *reinterpret_cast<const float4*>(&WB[(size_t)(nBase + n) * DEP_ + kk]);
        Bs[n][kk + 0] = b.x; Bs[n][kk + 1] = b.y;
        Bs[n][kk + 2] = b.z; Bs[n][kk + 3] = b.w;
    }
    __syncthreads();

    int ty = tid >> 4;
    int tx = tid & 15;
    float acc[4][4];
#pragma unroll
    for (int i = 0; i < 4; i++)
#pragma unroll
        for (int j = 0; j < 4; j++) acc[i][j] = 0.f;

#pragma unroll 8
    for (int k = 0; k < DEP_; k++) {
        float a[4], b[4];
#pragma unroll
        for (int i = 0; i < 4; i++) a[i] = As[ty * 4 + i][k];
#pragma unroll
        for (int j = 0; j < 4; j++) b[j] = Bs[tx * 4 + j][k];
#pragma unroll
        for (int i = 0; i < 4; i++)
#pragma unroll
            for (int j = 0; j < 4; j++) acc[i][j] = fmaf(a[i], b[j], acc[i][j]);
    }

#pragma unroll
    for (int i = 0; i < 4; i++) {
        int e = mBase + ty * 4 + i;
        int row = ei[e];
        int col = ei[E_ + e];
        float norm = g_dinv[row] * g_dinv[col];
        const float* axp = &g_Ax[(size_t)row * 256 + nBase + tx * 4];
        float* aggp = &g_agg[(size_t)col * 256 + nBase + tx * 4];
#pragma unroll
        for (int j = 0; j < 4; j++)
            atomicAdd(&aggp[j], norm * fast_tanh(axp[j] * acc[i][j]));
    }
}

__global__ void k_final_node(const float* __restrict__ bias) {
    int i = blockIdx.x;
    int j = threadIdx.x;
    float dv = g_dinv[i];
    size_t idx = (size_t)i * 256 + j;
    float self = dv * dv * fast_tanh(g_Ax[idx] * g_Bself[j]);
    float v = (g_agg[idx] + self) * __fdividef(1.f, g_deg[i]);
    g_seqA[idx] = fast_tanh(v + bias[j]);
}

// ---------------- GRU ----------------
// g_wT as float4[k4*768 + r] = {w[r][4k4..4k4+3]}
__global__ void k_wt(const float* __restrict__ w) {
    int idx = blockIdx.x * blockDim.x + threadIdx.x;   // 196608
    int c = idx & 3;
    int tmp = idx >> 2;
    int r = tmp % 768;
    int k4 = tmp / 768;
    g_wT[idx] = w[r * 256 + 4 * k4 + c];
}

// one block = 2 graphs; 256 threads; FFMA2 k-packed dot products;
// phase-double-buffered h => ONE __syncthreads per timestep.
__global__ void __launch_bounds__(256, 1)
k_gru(const float* __restrict__ b_hh, int outSel, int layer)
{
    float* seq_out = pick_buf(outSel);
    __shared__ __align__(16) float hs[2][2][256];   // [phase][graph][unit]
    int j = threadIdx.x;
    int b0 = blockIdx.x * 2;
    const ulonglong2* wt2 = reinterpret_cast<const ulonglong2*>(g_wT);

    float bR = b_hh[j], bZ = b_hh[256 + j], bN = b_hh[512 + j];
    const float* xp0 = g_xp + (size_t)(b0 + 0) * 256 * 768;
    const float* xp1 = g_xp + (size_t)(b0 + 1) * 256 * 768;

    hs[0][0][j] = 0.f; hs[0][1][j] = 0.f;
    __syncthreads();

    float hn0 = 0.f, hn1 = 0.f;
    for (int t = 0; t < 256; t++) {
        int ph = t & 1;
        const ulonglong2* h0v = reinterpret_cast<const ulonglong2*>(hs[ph][0]);
        const ulonglong2* h1v = reinterpret_cast<const ulonglong2*>(hs[ph][1]);
        // prefetch x-gate inputs (consumed after the dot-product loop)
        const float* x0 = xp0 + (size_t)t * 768;
        const float* x1 = xp1 + (size_t)t * 768;
        float xr0 = x0[j], xz0 = x0[256 + j], xn0 = x0[512 + j];
        float xr1 = x1[j], xz1 = x1[256 + j], xn1 = x1[512 + j];

        unsigned long long aR0 = 0, aZ0 = 0, aN0 = 0;
        unsigned long long aR1 = 0, aZ1 = 0, aN1 = 0;
#pragma unroll 4
        for (int k4 = 0; k4 < 64; k4++) {
            ulonglong2 w0 = wt2[k4 * 768 + j];          // r-gate row j
            ulonglong2 w1 = wt2[k4 * 768 + 256 + j];    // z-gate
            ulonglong2 w2 = wt2[k4 * 768 + 512 + j];    // n-gate
            ulonglong2 ha = h0v[k4];
            ulonglong2 hb = h1v[k4];
            ffma2(aR0, w0.x, ha.x); ffma2(aR0, w0.y, ha.y);
            ffma2(aZ0, w1.x, ha.x); ffma2(aZ0, w1.y, ha.y);
            ffma2(aN0, w2.x, ha.x); ffma2(aN0, w2.y, ha.y);
            ffma2(aR1, w0.x, hb.x); ffma2(aR1, w0.y, hb.y);
            ffma2(aZ1, w1.x, hb.x); ffma2(aZ1, w1.y, hb.y);
            ffma2(aN1, w2.x, hb.x); ffma2(aN1, w2.y, hb.y);
        }
        float hp0 = hs[ph][0][j], hp1 = hs[ph][1][j];
        {
            float r = fast_sig(xr0 + bR + hadd2(aR0));
            float z = fast_sig(xz0 + bZ + hadd2(aZ0));
            float n = fast_tanh(xn0 + r * (bN + hadd2(aN0)));
            hn0 = (1.f - z) * n + z * hp0;
        }
        {
            float r = fast_sig(xr1 + bR + hadd2(aR1));
            float z = fast_sig(xz1 + bZ + hadd2(aZ1));
            float n = fast_tanh(xn1 + r * (bN + hadd2(aN1)));
            hn1 = (1.f - z) * n + z * hp1;
        }
        hs[ph ^ 1][0][j] = hn0;
        hs[ph ^ 1][1][j] = hn1;
        seq_out[((size_t)(b0 + 0) * 256 + t) * 256 + j] = hn0;
        seq_out[((size_t)(b0 + 1) * 256 + t) * 256 + j] = hn1;
        __syncthreads();   // next-phase buffer complete; safe to overwrite cur
    }

    g_pool[(b0 + 0) * 1280 + layer * 256 + j] = hn0;
    g_pool[(b0 + 1) * 1280 + layer * 256 + j] = hn1;
}

// ---------------- pooling + head ----------------
__global__ void k_pool(int seqSel) {
    const float* seq = pick_buf(seqSel);
    int b = blockIdx.x, j = threadIdx.x;
    float m = -1e30f, s = 0.f;
#pragma unroll 4
    for (int t = 0; t < 256; t++) {
        float v = seq[((size_t)b * 256 + t) * 256 + j];
        m = fmaxf(m, v);
        s += v;
    }
    g_pool[b * 1280 + 768 + j] = m;
    g_pool[b * 1280 + 1024 + j] = s * (1.f / 256.f);
}

__global__ void k_head(const float* __restrict__ linW, const float* __restrict__ linb,
                       float* __restrict__ out)
{
    __shared__ float red0[128], red1[128];
    int b = blockIdx.x, tid = threadIdx.x;   // 128 threads
    float p0 = 0.f, p1 = 0.f;
    for (int i = tid; i < 1280; i += 128) {
        float pv = g_pool[b * 1280 + i];
        p0 = fmaf(pv, linW[i], p0);
        p1 = fmaf(pv, linW[1280 + i], p1);
    }
    red0[tid] = p0; red1[tid] = p1;
    __syncthreads();
    for (int s = 64; s > 0; s >>= 1) {
        if (tid < s) { red0[tid] += red0[tid + s]; red1[tid] += red1[tid + s]; }
        __syncthreads();
    }
    if (tid == 0) {
        float l0 = red0[0] + linb[0];
        float l1 = red1[0] + linb[1];
        float mm = fmaxf(l0, l1);
        float e0 = __expf(l0 - mm), e1 = __expf(l1 - mm);
        float inv = __fdividef(1.f, e0 + e1);
        out[b * 2 + 0] = e0 * inv;
        out[b * 2 + 1] = e1 * inv;
    }
}

// ---------------- launch (ONLY kernel launches — capture-clean) ----------------
extern "C" void kernel_launch(void* const* d_in, const int* in_sizes, int n_in,
                              void* d_out, int out_size)
{
    (void)in_sizes; (void)n_in; (void)out_size;
    const float* x    = (const float*)d_in[0];
    const float* ea   = (const float*)d_in[1];
    const int*   ei   = (const int*)  d_in[2];
    const float* WA   = (const float*)d_in[3];
    const float* WB   = (const float*)d_in[4];
    const float* gb   = (const float*)d_in[5];
    const float* wih[3] = {(const float*)d_in[6],  (const float*)d_in[10], (const float*)d_in[14]};
    const float* whh[3] = {(const float*)d_in[7],  (const float*)d_in[11], (const float*)d_in[15]};
    const float* bih[3] = {(const float*)d_in[8],  (const float*)d_in[12], (const float*)d_in[16]};
    const float* bhh[3] = {(const float*)d_in[9],  (const float*)d_in[13], (const float*)d_in[17]};
    const float* linW = (const float*)d_in[18];
    const float* linb = (const float*)d_in[19];
    float* out = (float*)d_out;

    // ---- GCN ----
    k_prep <<<NN_, 256>>>();
    k_count<<<E_ / 256, 256>>>(ei);
    k_dinv2<<<65, 256>>>(WB);
    sgemm2 <<<dim3(OUTC_ / BN2, NN_ / BM2), 256>>>(x, 0, WA, nullptr, BUF_AX,
                                                   OUTC_, FIN_);
    k_edge_fused<<<dim3(OUTC_ / 64, E_ / 64), 256>>>(ea, WB, ei);
    k_wt<<<G3_, 256>>>(whh[0]);
    k_final_node<<<NN_, 256>>>(gb);

    // ---- GRU: 3 layers (ping-pong seqA <-> seqB) ----
    int sin = BUF_SEQA, sout = BUF_SEQB;
    for (int l = 0; l < 3; l++) {
        if (l > 0) k_wt<<<G3_, 256>>>(whh[l]);
        sgemm2<<<dim3(G3_ / BN2, NN_ / BM2), 256>>>(nullptr, sin, wih[l], bih[l],
                                                    BUF_XP, G3_, 256);
        k_gru<<<B_ / 2, 256>>>(bhh[l], sout, l);
        int tmp = sin; sin = sout; sout = tmp;
    }
    // final layer output in `sin`

    // ---- pool + head ----
    k_pool<<<B_, 256>>>(sin);
    k_head<<<B_, 128>>>(linW, linb, out);
}

// round 12
// speedup vs baseline: 3.0100x; 1.8644x over previous
#include <cuda_runtime.h>
#include <math.h>
#include <stdint.h>

// Problem constants
#define NN_   16384      // total nodes (B*N)
#define E_    262144     // edges (no self loops)
#define B_    64         // graphs
#define FIN_  256
#define OUTC_ 256
#define DEP_  64
#define HID_  256
#define G3_   768        // 3*HID

// ---------------- device scratch (no cudaMalloc allowed) ----------------
__device__ __align__(16) float g_Ax  [NN_*OUTC_];
__device__ float g_deg [NN_];
__device__ float g_dinv[NN_];
__device__ __align__(16) float g_agg [NN_*OUTC_];
__device__ __align__(16) float g_seqA[NN_*OUTC_];
__device__ __align__(16) float g_seqB[NN_*OUTC_];
__device__ __align__(16) float g_xp  [NN_*G3_];
__device__ float g_Bself[OUTC_];
__device__ float g_pool[B_*1280];

// Device-side buffer selection (capture-clean host path: POD args only).
#define BUF_AX   1
#define BUF_SEQA 2
#define BUF_SEQB 3
#define BUF_XP   4
__device__ __forceinline__ float* pick_buf(int sel) {
    switch (sel) {
        case BUF_AX:   return g_Ax;
        case BUF_SEQA: return g_seqA;
        case BUF_SEQB: return g_seqB;
        default:       return g_xp;
    }
}

// ---------------- packed f32x2 + cluster helpers ----------------
__device__ __forceinline__ void ffma2(unsigned long long &d,
                                      unsigned long long a,
                                      unsigned long long b) {
    asm("fma.rn.f32x2 %0, %1, %2, %0;" : "+l"(d) : "l"(a), "l"(b));
}
__device__ __forceinline__ float hadd2(unsigned long long v) {
    float lo, hi;
    asm("mov.b64 {%0, %1}, %2;" : "=f"(lo), "=f"(hi) : "l"(v));
    return lo + hi;
}
__device__ __forceinline__ uint32_t smem_u32(const void* p) {
    uint32_t a;
    asm("{ .reg .u64 t; cvta.to.shared.u64 t, %1; cvt.u32.u64 %0, t; }"
        : "=r"(a) : "l"(p));
    return a;
}
__device__ __forceinline__ uint32_t ctarank() {
    uint32_t r; asm("mov.u32 %0, %%cluster_ctarank;" : "=r"(r)); return r;
}
__device__ __forceinline__ void st_cluster_f32(uint32_t laddr, uint32_t rank, float v) {
    uint32_t raddr;
    asm volatile("mapa.shared::cluster.u32 %0, %1, %2;" : "=r"(raddr) : "r"(laddr), "r"(rank));
    asm volatile("st.shared::cluster.f32 [%0], %1;" :: "r"(raddr), "f"(v) : "memory");
}
#define CLUSTER_SYNC() do { \
    asm volatile("barrier.cluster.arrive.aligned;" ::: "memory"); \
    asm volatile("barrier.cluster.wait.aligned;" ::: "memory"); } while (0)

// ---------------- math helpers (MUFU-based, ~1e-6 rel err) ----------------
__device__ __forceinline__ float fast_tanh(float x) {
    x = fminf(fmaxf(x, -15.f), 15.f);
    float e = __expf(2.f * x);
    return __fdividef(e - 1.f, e + 1.f);
}
__device__ __forceinline__ float fast_sig(float x) {
    x = fminf(fmaxf(x, -30.f), 30.f);
    return __fdividef(1.f, 1.f + __expf(-x));
}

// ---------------- SGEMM 128x128 scalar (R10 measured-best) ---------------
#define BM2 128
#define BN2 128
#define BK2 16
__global__ void __launch_bounds__(256)
sgemm2(const float* __restrict__ Aext, int aSel, const float* __restrict__ W,
       const float* __restrict__ bias, int cSel, int N, int K)
{
    const float* A = (aSel == 0) ? Aext : pick_buf(aSel);
    float* C = pick_buf(cSel);

    __shared__ float As[BK2][BM2 + 4];
    __shared__ float Bs[BK2][BN2 + 4];
    int tid = threadIdx.x;
    int mBase = blockIdx.y * BM2;
    int nBase = blockIdx.x * BN2;
    int ty = tid >> 4;
    int tx = tid & 15;

    float acc[8][8];
#pragma unroll
    for (int i = 0; i < 8; i++)
#pragma unroll
        for (int j = 0; j < 8; j++) acc[i][j] = 0.f;

    for (int kt = 0; kt < K; kt += BK2) {
#pragma unroll
        for (int u = 0; u < 2; u++) {
            int v = tid + u * 256;
            int row = v >> 2;
            int kk = (v & 3) * 4;
            float4 a = *reinterpret_cast<const float4*>(&A[(size_t)(mBase + row) * K + kt + kk]);
            As[kk + 0][row] = a.x; As[kk + 1][row] = a.y;
            As[kk + 2][row] = a.z; As[kk + 3][row] = a.w;
        }
#pragma unroll
        for (int u = 0; u < 2; u++) {
            int v = tid + u * 256;
            int n = v >> 2;
            int kk = (v & 3) * 4;
            float4 b = *reinterpret_cast<const float4*>(&W[(size_t)(nBase + n) * K + kt + kk]);
            Bs[kk + 0][n] = b.x; Bs[kk + 1][n] = b.y;
            Bs[kk + 2][n] = b.z; Bs[kk + 3][n] = b.w;
        }
        __syncthreads();
#pragma unroll
        for (int k = 0; k < BK2; k++) {
            float a[8], b[8];
            float4 a0 = *reinterpret_cast<const float4*>(&As[k][ty * 8]);
            float4 a1 = *reinterpret_cast<const float4*>(&As[k][ty * 8 + 4]);
            float4 b0 = *reinterpret_cast<const float4*>(&Bs[k][tx * 8]);
            float4 b1 = *reinterpret_cast<const float4*>(&Bs[k][tx * 8 + 4]);
            a[0]=a0.x; a[1]=a0.y; a[2]=a0.z; a[3]=a0.w;
            a[4]=a1.x; a[5]=a1.y; a[6]=a1.z; a[7]=a1.w;
            b[0]=b0.x; b[1]=b0.y; b[2]=b0.z; b[3]=b0.w;
            b[4]=b1.x; b[5]=b1.y; b[6]=b1.z; b[7]=b1.w;
#pragma unroll
            for (int i = 0; i < 8; i++)
#pragma unroll
                for (int j = 0; j < 8; j++) acc[i][j] = fmaf(a[i], b[j], acc[i][j]);
        }
        __syncthreads();
    }
#pragma unroll
    for (int i = 0; i < 8; i++) {
        int row = mBase + ty * 8 + i;
        int col = nBase + tx * 8;
#pragma unroll
        for (int h = 0; h < 2; h++) {
            float4 r = make_float4(acc[i][h*4+0], acc[i][h*4+1], acc[i][h*4+2], acc[i][h*4+3]);
            if (bias) {
                r.x += bias[col + h*4 + 0]; r.y += bias[col + h*4 + 1];
                r.z += bias[col + h*4 + 2]; r.w += bias[col + h*4 + 3];
            }
            *reinterpret_cast<float4*>(&C[(size_t)row * N + col + h*4]) = r;
        }
    }
}

// ---------------- GCN helper kernels ----------------
__global__ void k_prep() {
    int b = blockIdx.x, j = threadIdx.x;
    g_agg[(size_t)b * 256 + j] = 0.f;
    if (j == 0) g_deg[b] = 1.f;                 // self loop
}
__global__ void k_count(const int* __restrict__ ei) {
    int e = blockIdx.x * blockDim.x + threadIdx.x;
    if (e < E_) atomicAdd(&g_deg[ei[E_ + e]], 1.f);
}
__global__ void k_dinv2(const float* __restrict__ WB) {
    if (blockIdx.x < 64) {
        int i = blockIdx.x * 256 + threadIdx.x;
        g_dinv[i] = rsqrtf(g_deg[i]);
    } else {
        int j = threadIdx.x;
        float s = 0.f;
#pragma unroll
        for (int d = 0; d < DEP_; d++) s += WB[j * DEP_ + d];
        g_Bself[j] = s;
    }
}

// ---------------- fused edge kernel ----------------
__global__ void __launch_bounds__(256)
k_edge_fused(const float* __restrict__ ea, const float* __restrict__ WB,
             const int* __restrict__ ei)
{
    __shared__ float As[64][DEP_ + 1];
    __shared__ float Bs[64][DEP_ + 1];
    int tid = threadIdx.x;
    int mBase = blockIdx.y * 64;
    int nBase = blockIdx.x * 64;

#pragma unroll
    for (int u = 0; u < 4; u++) {
        int v = tid + u * 256;
        int row = v >> 4;
        int kk = (v & 15) * 4;
        float4 a = *reinterpret_cast<const float4*>(&ea[(size_t)(mBase + row) * DEP_ + kk]);
        As[row][kk + 0] = a.x; As[row][kk + 1] = a.y;
        As[row][kk + 2] = a.z; As[row][kk + 3] = a.w;
    }
#pragma unroll
    for (int u = 0; u < 4; u++) {
        int v = tid + u * 256;
        int n = v >> 4;
        int kk = (v & 15) * 4;
        float4 b = *reinterpret_cast<const float4*>(&WB[(size_t)(nBase + n) * DEP_ + kk]);
        Bs[n][kk + 0] = b.x; Bs[n][kk + 1] = b.y;
        Bs[n][kk + 2] = b.z; Bs[n][kk + 3] = b.w;
    }
    __syncthreads();

    int ty = tid >> 4;
    int tx = tid & 15;
    float acc[4][4];
#pragma unroll
    for (int i = 0; i < 4; i++)
#pragma unroll
        for (int j = 0; j < 4; j++) acc[i][j] = 0.f;

#pragma unroll 8
    for (int k = 0; k < DEP_; k++) {
        float a[4], b[4];
#pragma unroll
        for (int i = 0; i < 4; i++) a[i] = As[ty * 4 + i][k];
#pragma unroll
        for (int j = 0; j < 4; j++) b[j] = Bs[tx * 4 + j][k];
#pragma unroll
        for (int i = 0; i < 4; i++)
#pragma unroll
            for (int j = 0; j < 4; j++) acc[i][j] = fmaf(a[i], b[j], acc[i][j]);
    }

#pragma unroll
    for (int i = 0; i < 4; i++) {
        int e = mBase + ty * 4 + i;
        int row = ei[e];
        int col = ei[E_ + e];
        float norm = g_dinv[row] * g_dinv[col];
        const float* axp = &g_Ax[(size_t)row * 256 + nBase + tx * 4];
        float* aggp = &g_agg[(size_t)col * 256 + nBase + tx * 4];
#pragma unroll
        for (int j = 0; j < 4; j++)
            atomicAdd(&aggp[j], norm * fast_tanh(axp[j] * acc[i][j]));
    }
}

__global__ void k_final_node(const float* __restrict__ bias) {
    int i = blockIdx.x;
    int j = threadIdx.x;
    float dv = g_dinv[i];
    size_t idx = (size_t)i * 256 + j;
    float self = dv * dv * fast_tanh(g_Ax[idx] * g_Bself[j]);
    float v = (g_agg[idx] + self) * __fdividef(1.f, g_deg[i]);
    g_seqA[idx] = fast_tanh(v + bias[j]);
}

// ---------------- clustered GRU ----------------
// 4-CTA cluster per 2 graphs; CTA rank owns units [rank*64, rank*64+64)
// (gate rows {j, 256+j, 512+j}); weight slice (192 rows x 256 k) resident in
// smem for all 256 timesteps; h exchanged via DSMEM + 1 cluster.sync/step.
#define GRU_SMEM_FLOATS (192*260 + 2*2*256 + 2*192)
#define GRU_SMEM_BYTES  (GRU_SMEM_FLOATS * 4)

__global__ void __launch_bounds__(256, 1) __cluster_dims__(4, 1, 1)
k_gru(const float* __restrict__ whh, const float* __restrict__ b_hh,
      int outSel, int layer)
{
    extern __shared__ __align__(16) float smem[];
    float* w_s  = smem;                       // [192][260] (k padded 256->260)
    float* h_s  = smem + 192 * 260;           // [2][2][256] phase/graph/unit
    float* gh_s = h_s + 2 * 2 * 256;          // [2][192]    graph/(gate*64+j)

    float* seq_out = pick_buf(outSel);
    int tid = threadIdx.x;
    uint32_t rank = ctarank();
    int b0 = (blockIdx.x >> 2) * 2;

    // --- preload weight slice: local row lr = g*64 + j_loc -> whh row g*256 + rank*64 + j_loc
    const float4* w4 = reinterpret_cast<const float4*>(whh);
    for (int v = tid; v < 192 * 64; v += 256) {
        int lr = v >> 6, k4 = v & 63;
        int grow = (lr >> 6) * 256 + (int)rank * 64 + (lr & 63);
        *reinterpret_cast<float4*>(&w_s[lr * 260 + k4 * 4]) = w4[grow * 64 + k4];
    }
    if (tid < 256) { h_s[tid] = 0.f; h_s[256 + tid] = 0.f; }  // phase 0 zeros
    __syncthreads();
    CLUSTER_SYNC();

    // per-thread constants
    float my_bias = 0.f;
    const float* wrow = w_s;
    if (tid < 192) {
        my_bias = b_hh[(tid >> 6) * 256 + (int)rank * 64 + (tid & 63)];
        wrow = &w_s[tid * 260];
    }
    int gsel = (tid >> 6) & 1;            // combine threads tid<128
    int j_loc = tid & 63;
    int jg = (int)rank * 64 + j_loc;
    const float* xbase = g_xp + (size_t)(b0 + gsel) * 256 * 768;
    uint32_t h_s_base = smem_u32(h_s);

    float hn = 0.f;
    for (int t = 0; t < 256; t++) {
        int ph = t & 1;
        // prefetch x gates (combine threads only; consumed after dot loop)
        float xr = 0.f, xz = 0.f, xn = 0.f;
        if (tid < 128) {
            const float* xv = xbase + (size_t)t * 768;
            xr = xv[jg]; xz = xv[256 + jg]; xn = xv[512 + jg];
        }
        if (tid < 192) {
            const ulonglong2* hva = reinterpret_cast<const ulonglong2*>(&h_s[ph * 512]);
            const ulonglong2* hvb = reinterpret_cast<const ulonglong2*>(&h_s[ph * 512 + 256]);
            unsigned long long a0 = 0ull, a1 = 0ull;
#pragma unroll 8
            for (int k4 = 0; k4 < 64; k4++) {
                ulonglong2 w = *reinterpret_cast<const ulonglong2*>(&wrow[k4 * 4]);
                ulonglong2 ha = hva[k4];
                ulonglong2 hb = hvb[k4];
                ffma2(a0, w.x, ha.x); ffma2(a0, w.y, ha.y);
                ffma2(a1, w.x, hb.x); ffma2(a1, w.y, hb.y);
            }
            gh_s[tid]       = hadd2(a0) + my_bias;
            gh_s[192 + tid] = hadd2(a1) + my_bias;
        }
        __syncthreads();
        if (tid < 128) {
            const float* gh = &gh_s[gsel * 192];
            float r = fast_sig(xr + gh[j_loc]);
            float z = fast_sig(xz + gh[64 + j_loc]);
            float n = fast_tanh(xn + r * gh[128 + j_loc]);
            float hp = h_s[ph * 512 + gsel * 256 + jg];
            hn = (1.f - z) * n + z * hp;
            uint32_t laddr = h_s_base + (uint32_t)(((ph ^ 1) * 512 + gsel * 256 + jg) * 4);
#pragma unroll
            for (uint32_t r4 = 0; r4 < 4; r4++) st_cluster_f32(laddr, r4, hn);
            seq_out[((size_t)(b0 + gsel) * 256 + t) * 256 + jg] = hn;
        }
        CLUSTER_SYNC();
    }

    if (tid < 128)
        g_pool[(b0 + gsel) * 1280 + layer * 256 + jg] = hn;
}

// ---------------- pooling + head ----------------
__global__ void k_pool(int seqSel) {
    const float* seq = pick_buf(seqSel);
    int b = blockIdx.x, j = threadIdx.x;
    float m = -1e30f, s = 0.f;
#pragma unroll 4
    for (int t = 0; t < 256; t++) {
        float v = seq[((size_t)b * 256 + t) * 256 + j];
        m = fmaxf(m, v);
        s += v;
    }
    g_pool[b * 1280 + 768 + j] = m;
    g_pool[b * 1280 + 1024 + j] = s * (1.f / 256.f);
}

__global__ void k_head(const float* __restrict__ linW, const float* __restrict__ linb,
                       float* __restrict__ out)
{
    __shared__ float red0[128], red1[128];
    int b = blockIdx.x, tid = threadIdx.x;
    float p0 = 0.f, p1 = 0.f;
    for (int i = tid; i < 1280; i += 128) {
        float pv = g_pool[b * 1280 + i];
        p0 = fmaf(pv, linW[i], p0);
        p1 = fmaf(pv, linW[1280 + i], p1);
    }
    red0[tid] = p0; red1[tid] = p1;
    __syncthreads();
    for (int s = 64; s > 0; s >>= 1) {
        if (tid < s) { red0[tid] += red0[tid + s]; red1[tid] += red1[tid + s]; }
        __syncthreads();
    }
    if (tid == 0) {
        float l0 = red0[0] + linb[0];
        float l1 = red1[0] + linb[1];
        float mm = fmaxf(l0, l1);
        float e0 = __expf(l0 - mm), e1 = __expf(l1 - mm);
        float inv = __fdividef(1.f, e0 + e1);
        out[b * 2 + 0] = e0 * inv;
        out[b * 2 + 1] = e1 * inv;
    }
}

// ---------------- launch ----------------
extern "C" void kernel_launch(void* const* d_in, const int* in_sizes, int n_in,
                              void* d_out, int out_size)
{
    (void)in_sizes; (void)n_in; (void)out_size;
    const float* x    = (const float*)d_in[0];
    const float* ea   = (const float*)d_in[1];
    const int*   ei   = (const int*)  d_in[2];
    const float* WA   = (const float*)d_in[3];
    const float* WB   = (const float*)d_in[4];
    const float* gb   = (const float*)d_in[5];
    const float* wih[3] = {(const float*)d_in[6],  (const float*)d_in[10], (const float*)d_in[14]};
    const float* whh[3] = {(const float*)d_in[7],  (const float*)d_in[11], (const float*)d_in[15]};
    const float* bih[3] = {(const float*)d_in[8],  (const float*)d_in[12], (const float*)d_in[16]};
    const float* bhh[3] = {(const float*)d_in[9],  (const float*)d_in[13], (const float*)d_in[17]};
    const float* linW = (const float*)d_in[18];
    const float* linb = (const float*)d_in[19];
    float* out = (float*)d_out;

    // Opt-in to large dynamic smem for the clustered GRU (idempotent; not a
    // stream op, so legal during graph capture).
    cudaFuncSetAttribute(k_gru, cudaFuncAttributeMaxDynamicSharedMemorySize,
                         GRU_SMEM_BYTES);

    // ---- GCN ----
    k_prep <<<NN_, 256>>>();
    k_count<<<E_ / 256, 256>>>(ei);
    k_dinv2<<<65, 256>>>(WB);
    sgemm2 <<<dim3(OUTC_ / BN2, NN_ / BM2), 256>>>(x, 0, WA, nullptr, BUF_AX,
                                                   OUTC_, FIN_);
    k_edge_fused<<<dim3(OUTC_ / 64, E_ / 64), 256>>>(ea, WB, ei);
    k_final_node<<<NN_, 256>>>(gb);

    // ---- GRU: 3 layers (ping-pong seqA <-> seqB) ----
    int sin = BUF_SEQA, sout = BUF_SEQB;
    for (int l = 0; l < 3; l++) {
        sgemm2<<<dim3(G3_ / BN2, NN_ / BM2), 256>>>(nullptr, sin, wih[l], bih[l],
                                                    BUF_XP, G3_, 256);
        k_gru<<<(B_ / 2) * 4, 256, GRU_SMEM_BYTES>>>(whh[l], bhh[l], sout, l);
        int tmp = sin; sin = sout; sout = tmp;
    }
    // final layer output in `sin`

    // ---- pool + head ----
    k_pool<<<B_, 256>>>(sin);
    k_head<<<B_, 128>>>(linW, linb, out);
}

// round 15
// speedup vs baseline: 3.0697x; 1.0198x over previous
#include <cuda_runtime.h>
#include <math.h>
#include <stdint.h>

// Problem constants
#define NN_   16384      // total nodes (B*N)
#define E_    262144     // edges (no self loops)
#define B_    64         // graphs
#define FIN_  256
#define OUTC_ 256
#define DEP_  64
#define HID_  256
#define G3_   768        // 3*HID

// ---------------- device scratch (no cudaMalloc allowed) ----------------
// NOTE: __device__ globals are zero-initialized at module load; the tail
// kernel re-zeroes g_agg/g_deg after use so every graph replay starts clean.
__device__ __align__(16) float g_Ax  [NN_*OUTC_];
__device__ float g_deg [NN_];
__device__ float g_dinv[NN_];
__device__ __align__(16) float g_agg [NN_*OUTC_];
__device__ __align__(16) float g_seqA[NN_*OUTC_];
__device__ __align__(16) float g_seqB[NN_*OUTC_];
__device__ __align__(16) float g_xp  [NN_*G3_];
__device__ float g_Bself[OUTC_];
__device__ float g_pool[B_*1280];

// Device-side buffer selection (capture-clean host path: POD args only).
#define BUF_AX   1
#define BUF_SEQA 2
#define BUF_SEQB 3
#define BUF_XP   4
__device__ __forceinline__ float* pick_buf(int sel) {
    switch (sel) {
        case BUF_AX:   return g_Ax;
        case BUF_SEQA: return g_seqA;
        case BUF_SEQB: return g_seqB;
        default:       return g_xp;
    }
}

// ---------------- packed f32x2 + cluster + atomic helpers ----------------
__device__ __forceinline__ void ffma2(unsigned long long &d,
                                      unsigned long long a,
                                      unsigned long long b) {
    asm("fma.rn.f32x2 %0, %1, %2, %0;" : "+l"(d) : "l"(a), "l"(b));
}
__device__ __forceinline__ float hadd2(unsigned long long v) {
    float lo, hi;
    asm("mov.b64 {%0, %1}, %2;" : "=f"(lo), "=f"(hi) : "l"(v));
    return lo + hi;
}
__device__ __forceinline__ uint32_t smem_u32(const void* p) {
    uint32_t a;
    asm("{ .reg .u64 t; cvta.to.shared.u64 t, %1; cvt.u32.u64 %0, t; }"
        : "=r"(a) : "l"(p));
    return a;
}
__device__ __forceinline__ uint32_t ctarank() {
    uint32_t r; asm("mov.u32 %0, %%cluster_ctarank;" : "=r"(r)); return r;
}
__device__ __forceinline__ void st_cluster_f32(uint32_t laddr, uint32_t rank, float v) {
    uint32_t raddr;
    asm volatile("mapa.shared::cluster.u32 %0, %1, %2;" : "=r"(raddr) : "r"(laddr), "r"(rank));
    asm volatile("st.shared::cluster.f32 [%0], %1;" :: "r"(raddr), "f"(v) : "memory");
}
// vector reduction (sm_90+): 4 channels per atomic op, 16B-aligned address
__device__ __forceinline__ void red_add_v4(float* addr, float a, float b, float c, float d) {
    asm volatile("red.global.add.v4.f32 [%0], {%1, %2, %3, %4};"
                 :: "l"(addr), "f"(a), "f"(b), "f"(c), "f"(d) : "memory");
}
#define CLUSTER_SYNC() do { \
    asm volatile("barrier.cluster.arrive.aligned;" ::: "memory"); \
    asm volatile("barrier.cluster.wait.aligned;" ::: "memory"); } while (0)

// ---------------- math helpers (MUFU-based, ~1e-6 rel err) ----------------
__device__ __forceinline__ float fast_tanh(float x) {
    x = fminf(fmaxf(x, -15.f), 15.f);
    float e = __expf(2.f * x);
    return __fdividef(e - 1.f, e + 1.f);
}
__device__ __forceinline__ float fast_sig(float x) {
    x = fminf(fmaxf(x, -30.f), 30.f);
    return __fdividef(1.f, 1.f + __expf(-x));
}

// ---------------- SGEMM 128x128 scalar (measured-best) ---------------
#define BM2 128
#define BN2 128
#define BK2 16
__global__ void __launch_bounds__(256)
sgemm2(const float* __restrict__ Aext, int aSel, const float* __restrict__ W,
       const float* __restrict__ bias, int cSel, int N, int K)
{
    const float* A = (aSel == 0) ? Aext : pick_buf(aSel);
    float* C = pick_buf(cSel);

    __shared__ float As[BK2][BM2 + 4];
    __shared__ float Bs[BK2][BN2 + 4];
    int tid = threadIdx.x;
    int mBase = blockIdx.y * BM2;
    int nBase = blockIdx.x * BN2;
    int ty = tid >> 4;
    int tx = tid & 15;

    float acc[8][8];
#pragma unroll
    for (int i = 0; i < 8; i++)
#pragma unroll
        for (int j = 0; j < 8; j++) acc[i][j] = 0.f;

    for (int kt = 0; kt < K; kt += BK2) {
#pragma unroll
        for (int u = 0; u < 2; u++) {
            int v = tid + u * 256;
            int row = v >> 2;
            int kk = (v & 3) * 4;
            float4 a = *reinterpret_cast<const float4*>(&A[(size_t)(mBase + row) * K + kt + kk]);
            As[kk + 0][row] = a.x; As[kk + 1][row] = a.y;
            As[kk + 2][row] = a.z; As[kk + 3][row] = a.w;
        }
#pragma unroll
        for (int u = 0; u < 2; u++) {
            int v = tid + u * 256;
            int n = v >> 2;
            int kk = (v & 3) * 4;
            float4 b = *reinterpret_cast<const float4*>(&W[(size_t)(nBase + n) * K + kt + kk]);
            Bs[kk + 0][n] = b.x; Bs[kk + 1][n] = b.y;
            Bs[kk + 2][n] = b.z; Bs[kk + 3][n] = b.w;
        }
        __syncthreads();
#pragma unroll
        for (int k = 0; k < BK2; k++) {
            float a[8], b[8];
            float4 a0 = *reinterpret_cast<const float4*>(&As[k][ty * 8]);
            float4 a1 = *reinterpret_cast<const float4*>(&As[k][ty * 8 + 4]);
            float4 b0 = *reinterpret_cast<const float4*>(&Bs[k][tx * 8]);
            float4 b1 = *reinterpret_cast<const float4*>(&Bs[k][tx * 8 + 4]);
            a[0]=a0.x; a[1]=a0.y; a[2]=a0.z; a[3]=a0.w;
            a[4]=a1.x; a[5]=a1.y; a[6]=a1.z; a[7]=a1.w;
            b[0]=b0.x; b[1]=b0.y; b[2]=b0.z; b[3]=b0.w;
            b[4]=b1.x; b[5]=b1.y; b[6]=b1.z; b[7]=b1.w;
#pragma unroll
            for (int i = 0; i < 8; i++)
#pragma unroll
                for (int j = 0; j < 8; j++) acc[i][j] = fmaf(a[i], b[j], acc[i][j]);
        }
        __syncthreads();
    }
#pragma unroll
    for (int i = 0; i < 8; i++) {
        int row = mBase + ty * 8 + i;
        int col = nBase + tx * 8;
#pragma unroll
        for (int h = 0; h < 2; h++) {
            float4 r = make_float4(acc[i][h*4+0], acc[i][h*4+1], acc[i][h*4+2], acc[i][h*4+3]);
            if (bias) {
                r.x += bias[col + h*4 + 0]; r.y += bias[col + h*4 + 1];
                r.z += bias[col + h*4 + 2]; r.w += bias[col + h*4 + 3];
            }
            *reinterpret_cast<float4*>(&C[(size_t)row * N + col + h*4]) = r;
        }
    }
}

// ---------------- GCN helper kernels ----------------
// g_deg starts at 0 (module init / tail kernel); self-loop +1 folded into k_dinv2.
__global__ void k_count(const int* __restrict__ ei) {
    int e = blockIdx.x * blockDim.x + threadIdx.x;
    if (e < E_) atomicAdd(&g_deg[ei[E_ + e]], 1.f);
}
__global__ void k_dinv2(const float* __restrict__ WB) {
    if (blockIdx.x < 64) {
        int i = blockIdx.x * 256 + threadIdx.x;
        float d = g_deg[i] + 1.f;       // + self loop
        g_deg[i] = d;
        g_dinv[i] = rsqrtf(d);
    } else {
        int j = threadIdx.x;
        float s = 0.f;
#pragma unroll
        for (int d = 0; d < DEP_; d++) s += WB[j * DEP_ + d];
        g_Bself[j] = s;
    }
}

// ---------------- fused edge kernel (v4 vector reductions) ----------------
__global__ void __launch_bounds__(256)
k_edge_fused(const float* __restrict__ ea, const float* __restrict__ WB,
             const int* __restrict__ ei)
{
    __shared__ float As[64][DEP_ + 1];
    __shared__ float Bs[64][DEP_ + 1];
    int tid = threadIdx.x;
    int mBase = blockIdx.y * 64;
    int nBase = blockIdx.x * 64;

#pragma unroll
    for (int u = 0; u < 4; u++) {
        int v = tid + u * 256;
        int row = v >> 4;
        int kk = (v & 15) * 4;
        float4 a = *reinterpret_cast<const float4*>(&ea[(size_t)(mBase + row) * DEP_ + kk]);
        As[row][kk + 0] = a.x; As[row][kk + 1] = a.y;
        As[row][kk + 2] = a.z; As[row][kk + 3] = a.w;
    }
#pragma unroll
    for (int u = 0; u < 4; u++) {
        int v = tid + u * 256;
        int n = v >> 4;
        int kk = (v & 15) * 4;
        float4 b = *reinterpret_cast<const float4*>(&WB[(size_t)(nBase + n) * DEP_ + kk]);
        Bs[n][kk + 0] = b.x; Bs[n][kk + 1] = b.y;
        Bs[n][kk + 2] = b.z; Bs[n][kk + 3] = b.w;
    }
    __syncthreads();

    int ty = tid >> 4;
    int tx = tid & 15;
    float acc[4][4];
#pragma unroll
    for (int i = 0; i < 4; i++)
#pragma unroll
        for (int j = 0; j < 4; j++) acc[i][j] = 0.f;

#pragma unroll 8
    for (int k = 0; k < DEP_; k++) {
        float a[4], b[4];
#pragma unroll
        for (int i = 0; i < 4; i++) a[i] = As[ty * 4 + i][k];
#pragma unroll
        for (int j = 0; j < 4; j++) b[j] = Bs[tx * 4 + j][k];
#pragma unroll
        for (int i = 0; i < 4; i++)
#pragma unroll
            for (int j = 0; j < 4; j++) acc[i][j] = fmaf(a[i], b[j], acc[i][j]);
    }

#pragma unroll
    for (int i = 0; i < 4; i++) {
        int e = mBase + ty * 4 + i;
        int row = ei[e];
        int col = ei[E_ + e];
        float norm = g_dinv[row] * g_dinv[col];
        const float* axp = &g_Ax[(size_t)row * 256 + nBase + tx * 4];
        float* aggp = &g_agg[(size_t)col * 256 + nBase + tx * 4];
        red_add_v4(aggp,
                   norm * fast_tanh(axp[0] * acc[i][0]),
                   norm * fast_tanh(axp[1] * acc[i][1]),
                   norm * fast_tanh(axp[2] * acc[i][2]),
                   norm * fast_tanh(axp[3] * acc[i][3]));
    }
}

__global__ void k_final_node(const float* __restrict__ bias) {
    int i = blockIdx.x;
    int j = threadIdx.x;
    float dv = g_dinv[i];
    size_t idx = (size_t)i * 256 + j;
    float self = dv * dv * fast_tanh(g_Ax[idx] * g_Bself[j]);
    float v = (g_agg[idx] + self) * __fdividef(1.f, g_deg[i]);
    g_seqA[idx] = fast_tanh(v + bias[j]);
}

// tail: restore g_agg/g_deg to zero for the next (deterministic) replay
__global__ void k_tail() {
    int b = blockIdx.x, j = threadIdx.x;
    g_agg[(size_t)b * 256 + j] = 0.f;
    if (j == 0) g_deg[b] = 0.f;
}

// ---------------- clustered GRU ----------------
// 4-CTA cluster per 2 graphs; rank owns units [rank*64, rank*64+64)
// (gate rows {j, 256+j, 512+j}); weight slice resident in smem in
// CONFLICT-FREE [k4][row] layout (lane-contiguous 16B chunks).
#define GRU_SMEM_FLOATS (192*256 + 2*2*256 + 2*192)
#define GRU_SMEM_BYTES  (GRU_SMEM_FLOATS * 4)

__global__ void __launch_bounds__(256, 1) __cluster_dims__(4, 1, 1)
k_gru(const float* __restrict__ whh, const float* __restrict__ b_hh,
      int outSel, int layer)
{
    extern __shared__ __align__(16) float smem[];
    float* w_s  = smem;                       // [64][192] float4 = [k4][local row]
    float* h_s  = smem + 192 * 256;           // [2][2][256] phase/graph/unit
    float* gh_s = h_s + 2 * 2 * 256;          // [2][192]    graph/(gate*64+j)

    float* seq_out = pick_buf(outSel);
    int tid = threadIdx.x;
    uint32_t rank = ctarank();
    int b0 = (blockIdx.x >> 2) * 2;

    // preload weight slice: ws4[k4*192 + lr] = whh_row(lr)[4k4..4k4+3]
    // lr = gate*64 + j_loc  ->  global row gate*256 + rank*64 + j_loc
    const float4* w4 = reinterpret_cast<const float4*>(whh);
    float4* ws4 = reinterpret_cast<float4*>(w_s);
    for (int v = tid; v < 192 * 64; v += 256) {
        int lr = v % 192, k4 = v / 192;       // consecutive threads -> consecutive lr
        int grow = (lr >> 6) * 256 + (int)rank * 64 + (lr & 63);
        ws4[k4 * 192 + lr] = w4[grow * 64 + k4];
    }
    if (tid < 256) { h_s[tid] = 0.f; h_s[256 + tid] = 0.f; }  // phase 0 zeros
    __syncthreads();
    CLUSTER_SYNC();

    float my_bias = 0.f;
    if (tid < 192)
        my_bias = b_hh[(tid >> 6) * 256 + (int)rank * 64 + (tid & 63)];
    int gsel = (tid >> 6) & 1;            // combine threads: tid < 128
    int j_loc = tid & 63;
    int jg = (int)rank * 64 + j_loc;
    const float* xbase = g_xp + (size_t)(b0 + gsel) * 256 * 768;
    uint32_t h_s_base = smem_u32(h_s);
    const ulonglong2* wsv = reinterpret_cast<const ulonglong2*>(w_s);

    float hn = 0.f;
    for (int t = 0; t < 256; t++) {
        int ph = t & 1;
        float xr = 0.f, xz = 0.f, xn = 0.f;
        if (tid < 128) {
            const float* xv = xbase + (size_t)t * 768;
            xr = xv[jg]; xz = xv[256 + jg]; xn = xv[512 + jg];
        }
        if (tid < 192) {
            const ulonglong2* hva = reinterpret_cast<const ulonglong2*>(&h_s[ph * 512]);
            const ulonglong2* hvb = reinterpret_cast<const ulonglong2*>(&h_s[ph * 512 + 256]);
            unsigned long long a0 = 0ull, a1 = 0ull;
#pragma unroll 8
            for (int k4 = 0; k4 < 64; k4++) {
                ulonglong2 w = wsv[k4 * 192 + tid];    // lane-contiguous: conflict-free
                ulonglong2 ha = hva[k4];               // broadcast
                ulonglong2 hb = hvb[k4];
                ffma2(a0, w.x, ha.x); ffma2(a0, w.y, ha.y);
                ffma2(a1, w.x, hb.x); ffma2(a1, w.y, hb.y);
            }
            gh_s[tid]       = hadd2(a0) + my_bias;
            gh_s[192 + tid] = hadd2(a1) + my_bias;
        }
        __syncthreads();
        if (tid < 128) {
            const float* gh = &gh_s[gsel * 192];
            float r = fast_sig(xr + gh[j_loc]);
            float z = fast_sig(xz + gh[64 + j_loc]);
            float n = fast_tanh(xn + r * gh[128 + j_loc]);
            float hp = h_s[ph * 512 + gsel * 256 + jg];
            hn = (1.f - z) * n + z * hp;
            uint32_t laddr = h_s_base + (uint32_t)(((ph ^ 1) * 512 + gsel * 256 + jg) * 4);
#pragma unroll
            for (uint32_t r4 = 0; r4 < 4; r4++) st_cluster_f32(laddr, r4, hn);
            seq_out[((size_t)(b0 + gsel) * 256 + t) * 256 + jg] = hn;
        }
        CLUSTER_SYNC();
    }

    if (tid < 128)
        g_pool[(b0 + gsel) * 1280 + layer * 256 + jg] = hn;
}

// ---------------- pooling + head ----------------
__global__ void k_pool(int seqSel) {
    const float* seq = pick_buf(seqSel);
    int b = blockIdx.x, j = threadIdx.x;
    float m = -1e30f, s = 0.f;
#pragma unroll 4
    for (int t = 0; t < 256; t++) {
        float v = seq[((size_t)b * 256 + t) * 256 + j];
        m = fmaxf(m, v);
        s += v;
    }
    g_pool[b * 1280 + 768 + j] = m;
    g_pool[b * 1280 + 1024 + j] = s * (1.f / 256.f);
}

__global__ void k_head(const float* __restrict__ linW, const float* __restrict__ linb,
                       float* __restrict__ out)
{
    __shared__ float red0[128], red1[128];
    int b = blockIdx.x, tid = threadIdx.x;
    float p0 = 0.f, p1 = 0.f;
    for (int i = tid; i < 1280; i += 128) {
        float pv = g_pool[b * 1280 + i];
        p0 = fmaf(pv, linW[i], p0);
        p1 = fmaf(pv, linW[1280 + i], p1);
    }
    red0[tid] = p0; red1[tid] = p1;
    __syncthreads();
    for (int s = 64; s > 0; s >>= 1) {
        if (tid < s) { red0[tid] += red0[tid + s]; red1[tid] += red1[tid + s]; }
        __syncthreads();
    }
    if (tid == 0) {
        float l0 = red0[0] + linb[0];
        float l1 = red1[0] + linb[1];
        float mm = fmaxf(l0, l1);
        float e0 = __expf(l0 - mm), e1 = __expf(l1 - mm);
        float inv = __fdividef(1.f, e0 + e1);
        out[b * 2 + 0] = e0 * inv;
        out[b * 2 + 1] = e1 * inv;
    }
}

// ---------------- launch ----------------
extern "C" void kernel_launch(void* const* d_in, const int* in_sizes, int n_in,
                              void* d_out, int out_size)
{
    (void)in_sizes; (void)n_in; (void)out_size;
    const float* x    = (const float*)d_in[0];
    const float* ea   = (const float*)d_in[1];
    const int*   ei   = (const int*)  d_in[2];
    const float* WA   = (const float*)d_in[3];
    const float* WB   = (const float*)d_in[4];
    const float* gb   = (const float*)d_in[5];
    const float* wih[3] = {(const float*)d_in[6],  (const float*)d_in[10], (const float*)d_in[14]};
    const float* whh[3] = {(const float*)d_in[7],  (const float*)d_in[11], (const float*)d_in[15]};
    const float* bih[3] = {(const float*)d_in[8],  (const float*)d_in[12], (const float*)d_in[16]};
    const float* bhh[3] = {(const float*)d_in[9],  (const float*)d_in[13], (const float*)d_in[17]};
    const float* linW = (const float*)d_in[18];
    const float* linb = (const float*)d_in[19];
    float* out = (float*)d_out;

    cudaFuncSetAttribute(k_gru, cudaFuncAttributeMaxDynamicSharedMemorySize,
                         GRU_SMEM_BYTES);

    // ---- GCN (k_edge_fused is launch #4 -> gets the ncu profile slot) ----
    k_count<<<E_ / 256, 256>>>(ei);                                                // 1
    sgemm2 <<<dim3(OUTC_ / BN2, NN_ / BM2), 256>>>(x, 0, WA, nullptr, BUF_AX,
                                                   OUTC_, FIN_);                   // 2
    k_dinv2<<<65, 256>>>(WB);                                                      // 3
    k_edge_fused<<<dim3(OUTC_ / 64, E_ / 64), 256>>>(ea, WB, ei);                  // 4
    k_final_node<<<NN_, 256>>>(gb);                                                // 5
    k_tail<<<NN_, 256>>>();                                                        // 6

    // ---- GRU: 3 layers (ping-pong seqA <-> seqB) ----
    int sin = BUF_SEQA, sout = BUF_SEQB;
    for (int l = 0; l < 3; l++) {
        sgemm2<<<dim3(G3_ / BN2, NN_ / BM2), 256>>>(nullptr, sin, wih[l], bih[l],
                                                    BUF_XP, G3_, 256);
        k_gru<<<(B_ / 2) * 4, 256, GRU_SMEM_BYTES>>>(whh[l], bhh[l], sout, l);
        int tmp = sin; sin = sout; sout = tmp;
    }
    // final layer output in `sin`

    // ---- pool + head ----
    k_pool<<<B_, 256>>>(sin);
    k_head<<<B_, 128>>>(linW, linb, out);
}